// round 10
// baseline (speedup 1.0000x reference)
#include <cuda_runtime.h>
#include <cuda_fp16.h>
#include <math_constants.h>

#define BB 4
#define NN 2000
#define EE 64000
#define HH 64
#define PAD 128           // padded CSR row length
#define LOG2E 1.4426950408889634f

// ---------------- scratch ----------------
__device__ float g_M[3][3][5];        // folded (SCALE only, natural-log units) logit matrices
__device__ float g_F[12][128];        // Wv_t @ Wg[t-block, 64:192]
__device__ float g_czp[3][128];       // per-t partials of sum_t bv_t @ Wg[t-block, 64:192]
__device__ float g_vs[12], g_vd[12];  // Wv_t @ asfold/adfold[t-block]  (*log2e)
__device__ float g_hs[64], g_hd[64];  // asfold/adfold[192:256]         (*log2e)
__device__ float g_cs[2];             // const_s, const_d               (*log2e)
__device__ int   g_cnt[NN];           // INVARIANT: zero at kernel_launch entry
__device__ int   g_epad[NN * PAD];
__device__ float g_mom[12 * 1296];    // key moments deg<=5; INVARIANT: zero at entry
__device__ __half g_xzn[BB * NN * 128];
__device__ float g_als[BB * NN];
__device__ float g_ald[BB * NN];

__device__ __forceinline__ float ex2a(float x) {
    float y; asm("ex2.approx.ftz.f32 %0,%1;" : "=f"(y) : "f"(x)); return y;
}

// ---------------- K0a: folds (7 blocks) ----------------
__global__ void __launch_bounds__(256) k_fold(
        const float* Wq_a, const float* bq_a, const float* Wk_a, const float* bk_a,
        const float* Wq_b, const float* bq_b, const float* Wk_b, const float* bk_b,
        const float* Wq_c, const float* bq_c, const float* Wk_c, const float* bk_c,
        const float* Wv_a, const float* bv_a, const float* Wv_b, const float* bv_b,
        const float* Wv_c, const float* bv_c,
        const float* Wg, const float* att_src, const float* att_dst) {
    int tid = threadIdx.x;  // 256
    int bx = blockIdx.x;

    if (bx == 0) {
        __shared__ float s_src[192], s_dst[192];
        __shared__ float asf[256], adf[256];
        if (tid < 192) { s_src[tid] = att_src[tid]; s_dst[tid] = att_dst[tid]; }
        __syncthreads();
        int w = tid >> 5, lane = tid & 31;
#pragma unroll
        for (int g = 0; g < 8; g++) {
            int r = w * 32 + g * 4;
            float s0 = 0.f, s1 = 0.f, s2 = 0.f, s3 = 0.f;
            float d0 = 0.f, d1 = 0.f, d2 = 0.f, d3 = 0.f;
            for (int c = lane; c < 192; c += 32) {
                float a = s_src[c], dd = s_dst[c];
                float w0 = Wg[(r + 0) * 192 + c];
                float w1 = Wg[(r + 1) * 192 + c];
                float w2 = Wg[(r + 2) * 192 + c];
                float w3 = Wg[(r + 3) * 192 + c];
                s0 = fmaf(w0, a, s0); d0 = fmaf(w0, dd, d0);
                s1 = fmaf(w1, a, s1); d1 = fmaf(w1, dd, d1);
                s2 = fmaf(w2, a, s2); d2 = fmaf(w2, dd, d2);
                s3 = fmaf(w3, a, s3); d3 = fmaf(w3, dd, d3);
            }
#pragma unroll
            for (int off = 16; off; off >>= 1) {
                s0 += __shfl_xor_sync(0xffffffffu, s0, off);
                s1 += __shfl_xor_sync(0xffffffffu, s1, off);
                s2 += __shfl_xor_sync(0xffffffffu, s2, off);
                s3 += __shfl_xor_sync(0xffffffffu, s3, off);
                d0 += __shfl_xor_sync(0xffffffffu, d0, off);
                d1 += __shfl_xor_sync(0xffffffffu, d1, off);
                d2 += __shfl_xor_sync(0xffffffffu, d2, off);
                d3 += __shfl_xor_sync(0xffffffffu, d3, off);
            }
            if (lane == 0) {
                asf[r + 0] = s0; asf[r + 1] = s1; asf[r + 2] = s2; asf[r + 3] = s3;
                adf[r + 0] = d0; adf[r + 1] = d1; adf[r + 2] = d2; adf[r + 3] = d3;
            }
        }
        __syncthreads();
        if (tid < 45) {
            int t = tid / 15, rem = tid % 15, i = rem / 5, j = rem % 5;
            const float* Wq = (t == 0) ? Wq_a : (t == 1) ? Wq_b : Wq_c;
            const float* bq = (t == 0) ? bq_a : (t == 1) ? bq_b : bq_c;
            const float* Wk = (t == 0) ? Wk_a : (t == 1) ? Wk_b : Wk_c;
            const float* bk = (t == 0) ? bk_a : (t == 1) ? bk_b : bk_c;
            const float* qrow = (i < 2) ? (Wq + i * HH) : bq;
            const float* krow = (j < 4) ? (Wk + j * HH) : bk;
            float s = 0.f;
            for (int h = 0; h < HH; h++) s += qrow[h] * krow[h];
            g_M[t][i][j] = s * 0.125f;
        } else if (tid >= 64 && tid < 88) {
            int k = tid - 64;
            int sd = k / 12, kk = k % 12, t = kk / 4, i = kk % 4;
            const float* Wv = (t == 0) ? Wv_a : (t == 1) ? Wv_b : Wv_c;
            const float* f = sd ? adf : asf;
            float s = 0.f;
            for (int h = 0; h < HH; h++) s = fmaf(Wv[i * HH + h], f[t * 64 + h], s);
            if (sd) g_vd[kk] = s * LOG2E; else g_vs[kk] = s * LOG2E;
        } else if (tid >= 88 && tid < 152) {
            int k = tid - 88;
            g_hs[k] = asf[192 + k] * LOG2E;
            g_hd[k] = adf[192 + k] * LOG2E;
        } else if (tid >= 152 && tid < 154) {
            int sd = tid - 152;
            const float* f = sd ? adf : asf;
            float s = 0.f;
            for (int t = 0; t < 3; t++) {
                const float* bv = (t == 0) ? bv_a : (t == 1) ? bv_b : bv_c;
                for (int h = 0; h < HH; h++) s = fmaf(bv[h], f[t * 64 + h], s);
            }
            g_cs[sd] = s * LOG2E;
        }
    } else {
        // F fold (+ cz partial where rem<128 i.e. i==0)
        int idx = (bx - 1) * 256 + tid;
        int t = idx / 512, rem = idx % 512, i = rem / 128, c = rem % 128;
        const float* Wv = (t == 0) ? Wv_a : (t == 1) ? Wv_b : Wv_c;
        const float* bv = (t == 0) ? bv_a : (t == 1) ? bv_b : bv_c;
        bool do_cz = (rem < 128);
        float s = 0.f, s2 = 0.f;
        for (int h = 0; h < HH; h++) {
            float wg = Wg[(t * 64 + h) * 192 + 64 + c];
            s = fmaf(Wv[i * HH + h], wg, s);
            if (do_cz) s2 = fmaf(bv[h], wg, s2);
        }
        g_F[t * 4 + i][c] = s;
        if (do_cz) g_czp[t][c] = s2;
    }
}

// ---------------- K0b: key moments (96 blocks, 2 partial sums per monomial) ----------------
__global__ void __launch_bounds__(256) k_mom(const float* __restrict__ in) {
    __shared__ float ps[250][24];
    __shared__ int   mlist[126];
    __shared__ int   scnt;
    int tid = threadIdx.x;
    int m = blockIdx.x;
    int bt = m >> 3;
    int chunk = m & 7;
    int t = bt % 3, b = bt / 3;
    int kd0, kd1, kd2, kd3;
    if (t == 0) { kd0 = 2; kd1 = 3; kd2 = 4; kd3 = 5; }
    else if (t == 1) { kd0 = 0; kd1 = 1; kd2 = 4; kd3 = 5; }
    else { kd0 = 0; kd1 = 1; kd2 = 2; kd3 = 3; }
    if (tid == 0) scnt = 0;
    const float* inb = in + (size_t)b * NN * 6;
    if (tid < 250) {
        const float* r = inb + (chunk * 250 + tid) * 6;
        float kv0 = r[kd0], kv1 = r[kd1], kv2 = r[kd2], kv3 = r[kd3];
        float p0 = 1.f, p1 = 1.f, p2 = 1.f, p3 = 1.f;
#pragma unroll
        for (int e = 0; e < 6; e++) {
            ps[tid][e]      = p0;  p0 *= kv0;
            ps[tid][6 + e]  = p1;  p1 *= kv1;
            ps[tid][12 + e] = p2;  p2 *= kv2;
            ps[tid][18 + e] = p3;  p3 *= kv3;
        }
    }
    __syncthreads();
    for (int d = tid; d < 1296; d += 256) {
        int l4 = d % 6, k4 = (d / 6) % 6, j4 = (d / 36) % 6, i4 = d / 216;
        if (i4 + j4 + k4 + l4 <= 5) mlist[atomicAdd(&scnt, 1)] = d;
    }
    __syncthreads();
    {
        int half = tid >> 7;       // warps 0-3: keys 0-124, warps 4-7: keys 125-249
        int q = tid & 127;
        if (q < 126) {
            int d = mlist[q];
            int l4 = d % 6, k4 = (d / 6) % 6, j4 = (d / 36) % 6, i4 = d / 216;
            int k0 = half * 125, k1 = k0 + 125;
            float s = 0.f;
#pragma unroll 4
            for (int key = k0; key < k1; key++) {
                float a = ps[key][i4] * ps[key][6 + j4];
                float c = ps[key][12 + k4] * ps[key][18 + l4];
                s = fmaf(a, c, s);
            }
            atomicAdd(&g_mom[bt * 1296 + d], s);
        }
    }
}

// ---------------- K1: poly attention + x_zn GEMM + al_s/al_d (blocks 0-499)
//                     + CSR scatter (blocks 500-559) ----------------
__global__ void __launch_bounds__(256) k_xzn(const float* __restrict__ in,
                                             const float* __restrict__ hcur,
                                             const float* __restrict__ Wg,
                                             const int* __restrict__ edge) {
    int tid = threadIdx.x;  // 256
    if (blockIdx.x >= 500) {
        // CSR scatter (g_cnt zero at entry — reset by previous replay's k_agg)
        int base = (blockIdx.x - 500) * 256 + tid;
        for (int e = base; e < EE; e += 60 * 256) {
            int s = edge[e];
            int d = edge[EE + e];
            int pos = atomicAdd(&g_cnt[d], 1);
            if (pos < PAD) g_epad[d * PAD + pos] = s;
        }
        return;
    }

    __shared__ float4 Wh4[64][32];                 // 32 KB
    __shared__ __align__(16) float hrow[16][64];   // 4 KB
    __shared__ float  cn[16][12];
    __shared__ float  smomC[3][70][5];
    __shared__ int    wlist[70];
    __shared__ float  spow[8][20];
    __shared__ float  sgM[45];
    __shared__ int    scnt;
    int r0 = blockIdx.x * 16;
    int b = r0 / 2000;

    if (tid == 0) scnt = 0;

    for (int idx = tid; idx < 64 * 128; idx += 256) {
        int h = idx >> 7, c = idx & 127;
        ((float*)Wh4)[idx] = Wg[(192 + h) * 192 + 64 + c];
    }
    for (int idx = tid; idx < 16 * 64; idx += 256) {
        int i = idx >> 6, k = idx & 63;
        hrow[i][k] = hcur[(size_t)(r0 + i) * 64 + k];
    }
    if (tid < 45) sgM[tid] = ((const float*)g_M)[tid];
    __syncthreads();

    for (int d = tid; d < 1296; d += 256) {
        int l4 = d % 6, k4 = (d / 6) % 6, j4 = (d / 36) % 6, i4 = d / 216;
        if (i4 + j4 + k4 + l4 <= 4) wlist[atomicAdd(&scnt, 1)] = d;
    }
    __syncthreads();

    {
        const int STR[5] = {0, 216, 36, 6, 1};
        for (int idx = tid; idx < 3 * 70 * 5; idx += 256) {
            int t = idx / 350, r = idx % 350, q = r / 5, sl = r % 5;
            smomC[t][q][sl] = g_mom[(b * 3 + t) * 1296 + wlist[q] + STR[sl]];
        }
    }
    __syncthreads();

    int w = tid >> 5, lane = tid & 31;
    int rbase = w * 2;

    const float invf[5] = {1.f, 1.f, 0.5f, 0.16666667f, 0.041666668f};
#pragma unroll
    for (int rr = 0; rr < 2; rr++) {
        int i = rbase + rr;
        int n = (r0 + i) % 2000;
        const float* qrow = in + ((size_t)b * 2000 + n) * 6;
#pragma unroll
        for (int t = 0; t < 3; t++) {
            float a0 = qrow[2 * t], a1 = qrow[2 * t + 1];
            const float* Mt = &sgM[t * 15];
            float u0 = fmaf(a0, Mt[0], fmaf(a1, Mt[5], Mt[10]));
            float u1 = fmaf(a0, Mt[1], fmaf(a1, Mt[6], Mt[11]));
            float u2 = fmaf(a0, Mt[2], fmaf(a1, Mt[7], Mt[12]));
            float u3 = fmaf(a0, Mt[3], fmaf(a1, Mt[8], Mt[13]));
            if (lane < 20) {
                int v = lane / 5, e = lane % 5;
                float uv = (v == 0) ? u0 : (v == 1) ? u1 : (v == 2) ? u2 : u3;
                float p = invf[e];
                for (int x = 0; x < e; x++) p *= uv;
                spow[w][lane] = p;
            }
            __syncwarp();
            float dn = 0.f, c0 = 0.f, c1 = 0.f, c2 = 0.f, c3 = 0.f;
            for (int q = lane; q < 70; q += 32) {
                int d = wlist[q];
                int l4 = d % 6, k4 = (d / 6) % 6, j4 = (d / 36) % 6, i4 = d / 216;
                float wgt = spow[w][i4] * spow[w][5 + j4] * (spow[w][10 + k4] * spow[w][15 + l4]);
                dn = fmaf(wgt, smomC[t][q][0], dn);
                c0 = fmaf(wgt, smomC[t][q][1], c0);
                c1 = fmaf(wgt, smomC[t][q][2], c1);
                c2 = fmaf(wgt, smomC[t][q][3], c2);
                c3 = fmaf(wgt, smomC[t][q][4], c3);
            }
#pragma unroll
            for (int off = 16; off; off >>= 1) {
                dn += __shfl_xor_sync(0xffffffffu, dn, off);
                c0 += __shfl_xor_sync(0xffffffffu, c0, off);
                c1 += __shfl_xor_sync(0xffffffffu, c1, off);
                c2 += __shfl_xor_sync(0xffffffffu, c2, off);
                c3 += __shfl_xor_sync(0xffffffffu, c3, off);
            }
            if (lane == 0) {
                float inv = 1.0f / dn;
                cn[i][t * 4 + 0] = c0 * inv;
                cn[i][t * 4 + 1] = c1 * inv;
                cn[i][t * 4 + 2] = c2 * inv;
                cn[i][t * 4 + 3] = c3 * inv;
            }
            __syncwarp();
        }
    }
    __syncthreads();

    // ---- x_zn GEMM ----
    float4 czv;
    {
        float4 a = *(const float4*)&g_czp[0][lane * 4];
        float4 bq = *(const float4*)&g_czp[1][lane * 4];
        float4 c = *(const float4*)&g_czp[2][lane * 4];
        czv = make_float4(a.x + bq.x + c.x, a.y + bq.y + c.y,
                          a.z + bq.z + c.z, a.w + bq.w + c.w);
    }
    float4 acc0 = czv, acc1 = czv;

#pragma unroll
    for (int k = 0; k < 12; k++) {
        float4 f = *(const float4*)&g_F[k][lane * 4];
        float s0 = cn[rbase + 0][k], s1 = cn[rbase + 1][k];
        acc0.x = fmaf(s0, f.x, acc0.x); acc0.y = fmaf(s0, f.y, acc0.y);
        acc0.z = fmaf(s0, f.z, acc0.z); acc0.w = fmaf(s0, f.w, acc0.w);
        acc1.x = fmaf(s1, f.x, acc1.x); acc1.y = fmaf(s1, f.y, acc1.y);
        acc1.z = fmaf(s1, f.z, acc1.z); acc1.w = fmaf(s1, f.w, acc1.w);
    }

    const float4* h40 = (const float4*)hrow[rbase + 0];
    const float4* h41 = (const float4*)hrow[rbase + 1];
#pragma unroll 4
    for (int hq = 0; hq < 16; hq++) {
        float4 v0 = h40[hq], v1 = h41[hq];
#pragma unroll
        for (int j = 0; j < 4; j++) {
            float4 wv = Wh4[hq * 4 + j][lane];
            float e0 = j == 0 ? v0.x : j == 1 ? v0.y : j == 2 ? v0.z : v0.w;
            float e1 = j == 0 ? v1.x : j == 1 ? v1.y : j == 2 ? v1.z : v1.w;
            acc0.x = fmaf(e0, wv.x, acc0.x); acc0.y = fmaf(e0, wv.y, acc0.y);
            acc0.z = fmaf(e0, wv.z, acc0.z); acc0.w = fmaf(e0, wv.w, acc0.w);
            acc1.x = fmaf(e1, wv.x, acc1.x); acc1.y = fmaf(e1, wv.y, acc1.y);
            acc1.z = fmaf(e1, wv.z, acc1.z); acc1.w = fmaf(e1, wv.w, acc1.w);
        }
    }
    {
        __half2 p0 = __floats2half2_rn(acc0.x, acc0.y);
        __half2 p1 = __floats2half2_rn(acc0.z, acc0.w);
        __half2 q0 = __floats2half2_rn(acc1.x, acc1.y);
        __half2 q1 = __floats2half2_rn(acc1.z, acc1.w);
        *reinterpret_cast<__half2*>(&g_xzn[(size_t)(r0 + rbase + 0) * 128 + lane * 4])     = p0;
        *reinterpret_cast<__half2*>(&g_xzn[(size_t)(r0 + rbase + 0) * 128 + lane * 4 + 2]) = p1;
        *reinterpret_cast<__half2*>(&g_xzn[(size_t)(r0 + rbase + 1) * 128 + lane * 4])     = q0;
        *reinterpret_cast<__half2*>(&g_xzn[(size_t)(r0 + rbase + 1) * 128 + lane * 4 + 2]) = q1;
    }

#pragma unroll
    for (int rr = 0; rr < 2; rr++) {
        int i = rbase + rr;
        float s = hrow[i][lane] * g_hs[lane] + hrow[i][lane + 32] * g_hs[lane + 32];
        float d = hrow[i][lane] * g_hd[lane] + hrow[i][lane + 32] * g_hd[lane + 32];
#pragma unroll
        for (int off = 16; off; off >>= 1) {
            s += __shfl_xor_sync(0xffffffffu, s, off);
            d += __shfl_xor_sync(0xffffffffu, d, off);
        }
        if (lane == 0) {
            float ss = s + g_cs[0], dd = d + g_cs[1];
#pragma unroll
            for (int k = 0; k < 12; k++) {
                ss = fmaf(cn[i][k], g_vs[k], ss);
                dd = fmaf(cn[i][k], g_vd[k], dd);
            }
            g_als[r0 + i] = ss;
            g_ald[r0 + i] = dd;
        }
    }
}

// ---------------- K2: GAT aggregation + fused GRU — 2 nodes x 4 batches per block ----------------
__global__ void __launch_bounds__(256) k_agg(const float* __restrict__ hcur,
                                             const float* __restrict__ bg,
                                             float* __restrict__ out) {
    __shared__ int   sedge[2][PAD];
    __shared__ float sp[2][4][PAD];
    __shared__ int   sdeg[2];
    int tid = threadIdx.x;

    // deg snapshot + counter reset (each node owned by exactly one block)
    if (tid < 2) {
        int node2 = blockIdx.x * 2 + tid;
        int c = g_cnt[node2];
        sdeg[tid] = (c > PAD) ? PAD : c;
        g_cnt[node2] = 0;
    }
    // zero g_mom for next replay (k_agg never reads it); 61 blocks cover 15552
    {
        int z = blockIdx.x * 256 + tid;
        if (z < 12 * 1296) g_mom[z] = 0.f;
    }
    __syncthreads();

    int warp = tid >> 5, lane = tid & 31;
    int sub = warp >> 2;
    int bq  = warp & 3;
    int node = blockIdx.x * 2 + sub;

    int deg = sdeg[sub];
    const int* row = g_epad + node * PAD;
    if (bq == 0) {
        for (int i = lane; i < deg; i += 32) sedge[sub][i] = row[i];
    }
    __syncthreads();

    const float* als = g_als + bq * NN;
    float aldn = g_ald[bq * NN + node];

    float den = 0.f;
    for (int i = lane; i < deg; i += 32) {
        int s = sedge[sub][i];
        float ev = als[s] + aldn;
        ev = (ev >= 0.f) ? ev : 0.2f * ev;
        float p = ex2a(ev);
        sp[sub][bq][i] = p;
        den += p;
    }
#pragma unroll
    for (int off = 16; off; off >>= 1) den += __shfl_xor_sync(0xffffffffu, den, off);
    __syncwarp();

    float4 acc = make_float4(0.f, 0.f, 0.f, 0.f);
    const __half* xb = g_xzn + (size_t)bq * NN * 128;
#pragma unroll 4
    for (int e = 0; e < deg; e++) {
        int s = sedge[sub][e];
        float p = sp[sub][bq][e];
        uint2 v = *reinterpret_cast<const uint2*>(xb + (size_t)s * 128 + lane * 4);
        float2 f0 = __half22float2(*reinterpret_cast<const __half2*>(&v.x));
        float2 f1 = __half22float2(*reinterpret_cast<const __half2*>(&v.y));
        acc.x = fmaf(p, f0.x, acc.x);
        acc.y = fmaf(p, f0.y, acc.y);
        acc.z = fmaf(p, f1.x, acc.z);
        acc.w = fmaf(p, f1.y, acc.w);
    }
    float inv = 1.0f / (den + 1e-16f);
    int col = lane * 4;
    float v0 = acc.x * inv + bg[64 + col + 0];
    float v1 = acc.y * inv + bg[64 + col + 1];
    float v2 = acc.z * inv + bg[64 + col + 2];
    float v3 = acc.w * inv + bg[64 + col + 3];

    float a0, a1, a2, a3;
    if (lane < 16) {
        a0 = 1.0f / (1.0f + __expf(-v0));
        a1 = 1.0f / (1.0f + __expf(-v1));
        a2 = 1.0f / (1.0f + __expf(-v2));
        a3 = 1.0f / (1.0f + __expf(-v3));
    } else {
        a0 = tanhf(v0); a1 = tanhf(v1); a2 = tanhf(v2); a3 = tanhf(v3);
    }
    float n0 = __shfl_down_sync(0xffffffffu, a0, 16);
    float n1 = __shfl_down_sync(0xffffffffu, a1, 16);
    float n2 = __shfl_down_sync(0xffffffffu, a2, 16);
    float n3 = __shfl_down_sync(0xffffffffu, a3, 16);
    if (lane < 16) {
        const float4 h4 =
            *reinterpret_cast<const float4*>(hcur + ((size_t)bq * NN + node) * HH + lane * 4);
        float4 o;
        o.x = (1.f - a0) * n0 + a0 * h4.x;
        o.y = (1.f - a1) * n1 + a1 * h4.y;
        o.z = (1.f - a2) * n2 + a2 * h4.z;
        o.w = (1.f - a3) * n3 + a3 * h4.w;
        *reinterpret_cast<float4*>(out + ((size_t)bq * NN + node) * HH + lane * 4) = o;
    }
}

// ---------------- launch ----------------
extern "C" void kernel_launch(void* const* d_in, const int* in_sizes, int n_in,
                              void* d_out, int out_size) {
    const float* in   = (const float*)d_in[0];
    const float* hcur = (const float*)d_in[1];
    const int*   edge = (const int*)d_in[2];
    const float* Wq_a = (const float*)d_in[3];
    const float* bq_a = (const float*)d_in[4];
    const float* Wk_a = (const float*)d_in[5];
    const float* bk_a = (const float*)d_in[6];
    const float* Wv_a = (const float*)d_in[7];
    const float* bv_a = (const float*)d_in[8];
    const float* Wq_b = (const float*)d_in[9];
    const float* bq_b = (const float*)d_in[10];
    const float* Wk_b = (const float*)d_in[11];
    const float* bk_b = (const float*)d_in[12];
    const float* Wv_b = (const float*)d_in[13];
    const float* bv_b = (const float*)d_in[14];
    const float* Wq_c = (const float*)d_in[15];
    const float* bq_c = (const float*)d_in[16];
    const float* Wk_c = (const float*)d_in[17];
    const float* bk_c = (const float*)d_in[18];
    const float* Wv_c = (const float*)d_in[19];
    const float* bv_c = (const float*)d_in[20];
    const float* Wg      = (const float*)d_in[21];
    const float* att_src = (const float*)d_in[22];
    const float* att_dst = (const float*)d_in[23];
    const float* bg      = (const float*)d_in[24];
    float* out = (float*)d_out;

    k_fold<<<7, 256>>>(Wq_a, bq_a, Wk_a, bk_a, Wq_b, bq_b, Wk_b, bk_b,
                       Wq_c, bq_c, Wk_c, bk_c,
                       Wv_a, bv_a, Wv_b, bv_b, Wv_c, bv_c,
                       Wg, att_src, att_dst);
    k_mom<<<96, 256>>>(in);
    k_xzn<<<560, 256>>>(in, hcur, Wg, edge);
    k_agg<<<1000, 256>>>(hcur, bg, out);
}

// round 11
// speedup vs baseline: 1.1144x; 1.1144x over previous
#include <cuda_runtime.h>
#include <cuda_fp16.h>
#include <math_constants.h>

#define BB 4
#define NN 2000
#define EE 64000
#define HH 64
#define PAD 128           // padded CSR row length
#define LOG2E 1.4426950408889634f

// ---------------- scratch ----------------
__device__ float g_M[3][3][5];        // folded (SCALE only, natural-log units) logit matrices
__device__ float g_F[12][128];        // Wv_t @ Wg[t-block, 64:192]
__device__ float g_czp[3][128];       // per-t partials of sum_t bv_t @ Wg[t-block, 64:192]
__device__ float g_vs[12], g_vd[12];  // Wv_t @ asfold/adfold[t-block]  (*log2e)
__device__ float g_hs[64], g_hd[64];  // asfold/adfold[192:256]         (*log2e)
__device__ float g_cs[2];             // const_s, const_d               (*log2e)
__device__ int   g_cnt[NN];           // INVARIANT: zero at kernel_launch entry
__device__ int   g_deg[NN];
__device__ int   g_epad[NN * PAD];
__device__ float g_mom[12 * 1296];    // key moments deg<=5; INVARIANT: zero at entry
__device__ __half g_xzn[BB * NN * 128];
__device__ float g_als[BB * NN];
__device__ float g_ald[BB * NN];

__device__ __forceinline__ float ex2a(float x) {
    float y; asm("ex2.approx.ftz.f32 %0,%1;" : "=f"(y) : "f"(x)); return y;
}

// ---------------- K0: folds (blocks 0-6) + moments (7-102) + CSR (103-162) ----------------
__global__ void __launch_bounds__(256) k_pre(
        const float* __restrict__ in, const int* __restrict__ edge,
        const float* Wq_a, const float* bq_a, const float* Wk_a, const float* bk_a,
        const float* Wq_b, const float* bq_b, const float* Wk_b, const float* bk_b,
        const float* Wq_c, const float* bq_c, const float* Wk_c, const float* bk_c,
        const float* Wv_a, const float* bv_a, const float* Wv_b, const float* bv_b,
        const float* Wv_c, const float* bv_c,
        const float* Wg, const float* att_src, const float* att_dst) {
    int tid = threadIdx.x;  // 256
    int bx = blockIdx.x;

    if (bx >= 103) {
        // CSR scatter (g_cnt zero at entry)
        int base = (bx - 103) * 256 + tid;
        for (int e = base; e < EE; e += 60 * 256) {
            int s = edge[e];
            int d = edge[EE + e];
            int pos = atomicAdd(&g_cnt[d], 1);
            if (pos < PAD) g_epad[d * PAD + pos] = s;
        }
        return;
    }
    if (bx >= 7) {
        // ---- key moments for one (b,t,chunk); 2 half-key partial sums per monomial ----
        __shared__ float ps[250][24];
        __shared__ int   mlist[126];
        __shared__ int   scnt;
        int m = bx - 7;
        int bt = m >> 3;
        int chunk = m & 7;
        int t = bt % 3, b = bt / 3;
        int kd0, kd1, kd2, kd3;
        if (t == 0) { kd0 = 2; kd1 = 3; kd2 = 4; kd3 = 5; }
        else if (t == 1) { kd0 = 0; kd1 = 1; kd2 = 4; kd3 = 5; }
        else { kd0 = 0; kd1 = 1; kd2 = 2; kd3 = 3; }
        if (tid == 0) scnt = 0;
        const float* inb = in + (size_t)b * NN * 6;
        if (tid < 250) {
            const float* r = inb + (chunk * 250 + tid) * 6;
            float kv0 = r[kd0], kv1 = r[kd1], kv2 = r[kd2], kv3 = r[kd3];
            float p0 = 1.f, p1 = 1.f, p2 = 1.f, p3 = 1.f;
#pragma unroll
            for (int e = 0; e < 6; e++) {
                ps[tid][e]      = p0;  p0 *= kv0;
                ps[tid][6 + e]  = p1;  p1 *= kv1;
                ps[tid][12 + e] = p2;  p2 *= kv2;
                ps[tid][18 + e] = p3;  p3 *= kv3;
            }
        }
        __syncthreads();
        for (int d = tid; d < 1296; d += 256) {
            int l4 = d % 6, k4 = (d / 6) % 6, j4 = (d / 36) % 6, i4 = d / 216;
            if (i4 + j4 + k4 + l4 <= 5) mlist[atomicAdd(&scnt, 1)] = d;
        }
        __syncthreads();
        {
            int half = tid >> 7;       // warps 0-3: keys 0-124, warps 4-7: keys 125-249
            int q = tid & 127;
            if (q < 126) {
                int d = mlist[q];
                int l4 = d % 6, k4 = (d / 6) % 6, j4 = (d / 36) % 6, i4 = d / 216;
                int k0 = half * 125, k1 = k0 + 125;
                float s = 0.f;
#pragma unroll 4
                for (int key = k0; key < k1; key++) {
                    float a = ps[key][i4] * ps[key][6 + j4];
                    float c = ps[key][12 + k4] * ps[key][18 + l4];
                    s = fmaf(a, c, s);
                }
                atomicAdd(&g_mom[bt * 1296 + d], s);
            }
        }
        return;
    }

    // ---- fold blocks ----
    if (bx == 0) {
        __shared__ float s_src[192], s_dst[192];
        __shared__ float asf[256], adf[256];
        if (tid < 192) { s_src[tid] = att_src[tid]; s_dst[tid] = att_dst[tid]; }
        __syncthreads();
        int w = tid >> 5, lane = tid & 31;
#pragma unroll
        for (int g = 0; g < 8; g++) {
            int r = w * 32 + g * 4;
            float s0 = 0.f, s1 = 0.f, s2 = 0.f, s3 = 0.f;
            float d0 = 0.f, d1 = 0.f, d2 = 0.f, d3 = 0.f;
            for (int c = lane; c < 192; c += 32) {
                float a = s_src[c], dd = s_dst[c];
                float w0 = Wg[(r + 0) * 192 + c];
                float w1 = Wg[(r + 1) * 192 + c];
                float w2 = Wg[(r + 2) * 192 + c];
                float w3 = Wg[(r + 3) * 192 + c];
                s0 = fmaf(w0, a, s0); d0 = fmaf(w0, dd, d0);
                s1 = fmaf(w1, a, s1); d1 = fmaf(w1, dd, d1);
                s2 = fmaf(w2, a, s2); d2 = fmaf(w2, dd, d2);
                s3 = fmaf(w3, a, s3); d3 = fmaf(w3, dd, d3);
            }
#pragma unroll
            for (int off = 16; off; off >>= 1) {
                s0 += __shfl_xor_sync(0xffffffffu, s0, off);
                s1 += __shfl_xor_sync(0xffffffffu, s1, off);
                s2 += __shfl_xor_sync(0xffffffffu, s2, off);
                s3 += __shfl_xor_sync(0xffffffffu, s3, off);
                d0 += __shfl_xor_sync(0xffffffffu, d0, off);
                d1 += __shfl_xor_sync(0xffffffffu, d1, off);
                d2 += __shfl_xor_sync(0xffffffffu, d2, off);
                d3 += __shfl_xor_sync(0xffffffffu, d3, off);
            }
            if (lane == 0) {
                asf[r + 0] = s0; asf[r + 1] = s1; asf[r + 2] = s2; asf[r + 3] = s3;
                adf[r + 0] = d0; adf[r + 1] = d1; adf[r + 2] = d2; adf[r + 3] = d3;
            }
        }
        __syncthreads();
        if (tid < 45) {
            int t = tid / 15, rem = tid % 15, i = rem / 5, j = rem % 5;
            const float* Wq = (t == 0) ? Wq_a : (t == 1) ? Wq_b : Wq_c;
            const float* bq = (t == 0) ? bq_a : (t == 1) ? bq_b : bq_c;
            const float* Wk = (t == 0) ? Wk_a : (t == 1) ? Wk_b : Wk_c;
            const float* bk = (t == 0) ? bk_a : (t == 1) ? bk_b : bk_c;
            const float* qrow = (i < 2) ? (Wq + i * HH) : bq;
            const float* krow = (j < 4) ? (Wk + j * HH) : bk;
            float s = 0.f;
            for (int h = 0; h < HH; h++) s += qrow[h] * krow[h];
            g_M[t][i][j] = s * 0.125f;
        } else if (tid >= 64 && tid < 88) {
            int k = tid - 64;
            int sd = k / 12, kk = k % 12, t = kk / 4, i = kk % 4;
            const float* Wv = (t == 0) ? Wv_a : (t == 1) ? Wv_b : Wv_c;
            const float* f = sd ? adf : asf;
            float s = 0.f;
            for (int h = 0; h < HH; h++) s = fmaf(Wv[i * HH + h], f[t * 64 + h], s);
            if (sd) g_vd[kk] = s * LOG2E; else g_vs[kk] = s * LOG2E;
        } else if (tid >= 88 && tid < 152) {
            int k = tid - 88;
            g_hs[k] = asf[192 + k] * LOG2E;
            g_hd[k] = adf[192 + k] * LOG2E;
        } else if (tid >= 152 && tid < 154) {
            int sd = tid - 152;
            const float* f = sd ? adf : asf;
            float s = 0.f;
            for (int t = 0; t < 3; t++) {
                const float* bv = (t == 0) ? bv_a : (t == 1) ? bv_b : bv_c;
                for (int h = 0; h < HH; h++) s = fmaf(bv[h], f[t * 64 + h], s);
            }
            g_cs[sd] = s * LOG2E;
        }
    } else {
        // F fold (+ cz partial where rem<128 i.e. i==0)
        int idx = (bx - 1) * 256 + tid;
        int t = idx / 512, rem = idx % 512, i = rem / 128, c = rem % 128;
        const float* Wv = (t == 0) ? Wv_a : (t == 1) ? Wv_b : Wv_c;
        const float* bv = (t == 0) ? bv_a : (t == 1) ? bv_b : bv_c;
        bool do_cz = (rem < 128);
        float s = 0.f, s2 = 0.f;
        for (int h = 0; h < HH; h++) {
            float wg = Wg[(t * 64 + h) * 192 + 64 + c];
            s = fmaf(Wv[i * HH + h], wg, s);
            if (do_cz) s2 = fmaf(bv[h], wg, s2);
        }
        g_F[t * 4 + i][c] = s;
        if (do_cz) g_czp[t][c] = s2;
    }
}

// ---------------- K1: poly attention + x_zn GEMM + al_s/al_d — 16 rows/block ----------------
__global__ void __launch_bounds__(256) k_xzn(const float* __restrict__ in,
                                             const float* __restrict__ hcur,
                                             const float* __restrict__ Wg) {
    __shared__ float4 Wh4[64][32];                 // 32 KB
    __shared__ __align__(16) float hrow[16][64];   // 4 KB
    __shared__ float  cn[16][12];
    __shared__ float  smomC[3][70][5];
    __shared__ int    wlist[70];
    __shared__ float  spow[8][20];
    __shared__ float  sgM[45];
    __shared__ int    scnt;
    int tid = threadIdx.x;  // 256
    int r0 = blockIdx.x * 16;
    int b = r0 / 2000;

    if (tid == 0) scnt = 0;

    // snapshot degree + reset counters for next replay (invariant: g_cnt==0 at entry)
    {
        int gidx = blockIdx.x * 256 + tid;
        if (gidx < NN) {
            int c = g_cnt[gidx];
            g_deg[gidx] = (c > PAD) ? PAD : c;
            g_cnt[gidx] = 0;
        }
    }

    for (int idx = tid; idx < 64 * 128; idx += 256) {
        int h = idx >> 7, c = idx & 127;
        ((float*)Wh4)[idx] = Wg[(192 + h) * 192 + 64 + c];
    }
    for (int idx = tid; idx < 16 * 64; idx += 256) {
        int i = idx >> 6, k = idx & 63;
        hrow[i][k] = hcur[(size_t)(r0 + i) * 64 + k];
    }
    if (tid < 45) sgM[tid] = ((const float*)g_M)[tid];
    __syncthreads();

    for (int d = tid; d < 1296; d += 256) {
        int l4 = d % 6, k4 = (d / 6) % 6, j4 = (d / 36) % 6, i4 = d / 216;
        if (i4 + j4 + k4 + l4 <= 4) wlist[atomicAdd(&scnt, 1)] = d;
    }
    __syncthreads();

    {
        const int STR[5] = {0, 216, 36, 6, 1};
        for (int idx = tid; idx < 3 * 70 * 5; idx += 256) {
            int t = idx / 350, r = idx % 350, q = r / 5, sl = r % 5;
            smomC[t][q][sl] = g_mom[(b * 3 + t) * 1296 + wlist[q] + STR[sl]];
        }
    }
    __syncthreads();

    int w = tid >> 5, lane = tid & 31;
    int rbase = w * 2;

    const float invf[5] = {1.f, 1.f, 0.5f, 0.16666667f, 0.041666668f};
#pragma unroll
    for (int rr = 0; rr < 2; rr++) {
        int i = rbase + rr;
        int n = (r0 + i) % 2000;
        const float* qrow = in + ((size_t)b * 2000 + n) * 6;
#pragma unroll
        for (int t = 0; t < 3; t++) {
            float a0 = qrow[2 * t], a1 = qrow[2 * t + 1];
            const float* Mt = &sgM[t * 15];
            float u0 = fmaf(a0, Mt[0], fmaf(a1, Mt[5], Mt[10]));
            float u1 = fmaf(a0, Mt[1], fmaf(a1, Mt[6], Mt[11]));
            float u2 = fmaf(a0, Mt[2], fmaf(a1, Mt[7], Mt[12]));
            float u3 = fmaf(a0, Mt[3], fmaf(a1, Mt[8], Mt[13]));
            if (lane < 20) {
                int v = lane / 5, e = lane % 5;
                float uv = (v == 0) ? u0 : (v == 1) ? u1 : (v == 2) ? u2 : u3;
                float p = invf[e];
                for (int x = 0; x < e; x++) p *= uv;
                spow[w][lane] = p;
            }
            __syncwarp();
            float dn = 0.f, c0 = 0.f, c1 = 0.f, c2 = 0.f, c3 = 0.f;
            for (int q = lane; q < 70; q += 32) {
                int d = wlist[q];
                int l4 = d % 6, k4 = (d / 6) % 6, j4 = (d / 36) % 6, i4 = d / 216;
                float wgt = spow[w][i4] * spow[w][5 + j4] * (spow[w][10 + k4] * spow[w][15 + l4]);
                dn = fmaf(wgt, smomC[t][q][0], dn);
                c0 = fmaf(wgt, smomC[t][q][1], c0);
                c1 = fmaf(wgt, smomC[t][q][2], c1);
                c2 = fmaf(wgt, smomC[t][q][3], c2);
                c3 = fmaf(wgt, smomC[t][q][4], c3);
            }
#pragma unroll
            for (int off = 16; off; off >>= 1) {
                dn += __shfl_xor_sync(0xffffffffu, dn, off);
                c0 += __shfl_xor_sync(0xffffffffu, c0, off);
                c1 += __shfl_xor_sync(0xffffffffu, c1, off);
                c2 += __shfl_xor_sync(0xffffffffu, c2, off);
                c3 += __shfl_xor_sync(0xffffffffu, c3, off);
            }
            if (lane == 0) {
                float inv = 1.0f / dn;
                cn[i][t * 4 + 0] = c0 * inv;
                cn[i][t * 4 + 1] = c1 * inv;
                cn[i][t * 4 + 2] = c2 * inv;
                cn[i][t * 4 + 3] = c3 * inv;
            }
            __syncwarp();
        }
    }
    __syncthreads();

    // ---- x_zn GEMM ----
    float4 czv;
    {
        float4 a = *(const float4*)&g_czp[0][lane * 4];
        float4 bq = *(const float4*)&g_czp[1][lane * 4];
        float4 c = *(const float4*)&g_czp[2][lane * 4];
        czv = make_float4(a.x + bq.x + c.x, a.y + bq.y + c.y,
                          a.z + bq.z + c.z, a.w + bq.w + c.w);
    }
    float4 acc0 = czv, acc1 = czv;

#pragma unroll
    for (int k = 0; k < 12; k++) {
        float4 f = *(const float4*)&g_F[k][lane * 4];
        float s0 = cn[rbase + 0][k], s1 = cn[rbase + 1][k];
        acc0.x = fmaf(s0, f.x, acc0.x); acc0.y = fmaf(s0, f.y, acc0.y);
        acc0.z = fmaf(s0, f.z, acc0.z); acc0.w = fmaf(s0, f.w, acc0.w);
        acc1.x = fmaf(s1, f.x, acc1.x); acc1.y = fmaf(s1, f.y, acc1.y);
        acc1.z = fmaf(s1, f.z, acc1.z); acc1.w = fmaf(s1, f.w, acc1.w);
    }

    const float4* h40 = (const float4*)hrow[rbase + 0];
    const float4* h41 = (const float4*)hrow[rbase + 1];
#pragma unroll 4
    for (int hq = 0; hq < 16; hq++) {
        float4 v0 = h40[hq], v1 = h41[hq];
#pragma unroll
        for (int j = 0; j < 4; j++) {
            float4 wv = Wh4[hq * 4 + j][lane];
            float e0 = j == 0 ? v0.x : j == 1 ? v0.y : j == 2 ? v0.z : v0.w;
            float e1 = j == 0 ? v1.x : j == 1 ? v1.y : j == 2 ? v1.z : v1.w;
            acc0.x = fmaf(e0, wv.x, acc0.x); acc0.y = fmaf(e0, wv.y, acc0.y);
            acc0.z = fmaf(e0, wv.z, acc0.z); acc0.w = fmaf(e0, wv.w, acc0.w);
            acc1.x = fmaf(e1, wv.x, acc1.x); acc1.y = fmaf(e1, wv.y, acc1.y);
            acc1.z = fmaf(e1, wv.z, acc1.z); acc1.w = fmaf(e1, wv.w, acc1.w);
        }
    }
    {
        __half2 p0 = __floats2half2_rn(acc0.x, acc0.y);
        __half2 p1 = __floats2half2_rn(acc0.z, acc0.w);
        __half2 q0 = __floats2half2_rn(acc1.x, acc1.y);
        __half2 q1 = __floats2half2_rn(acc1.z, acc1.w);
        *reinterpret_cast<__half2*>(&g_xzn[(size_t)(r0 + rbase + 0) * 128 + lane * 4])     = p0;
        *reinterpret_cast<__half2*>(&g_xzn[(size_t)(r0 + rbase + 0) * 128 + lane * 4 + 2]) = p1;
        *reinterpret_cast<__half2*>(&g_xzn[(size_t)(r0 + rbase + 1) * 128 + lane * 4])     = q0;
        *reinterpret_cast<__half2*>(&g_xzn[(size_t)(r0 + rbase + 1) * 128 + lane * 4 + 2]) = q1;
    }

#pragma unroll
    for (int rr = 0; rr < 2; rr++) {
        int i = rbase + rr;
        float s = hrow[i][lane] * g_hs[lane] + hrow[i][lane + 32] * g_hs[lane + 32];
        float d = hrow[i][lane] * g_hd[lane] + hrow[i][lane + 32] * g_hd[lane + 32];
#pragma unroll
        for (int off = 16; off; off >>= 1) {
            s += __shfl_xor_sync(0xffffffffu, s, off);
            d += __shfl_xor_sync(0xffffffffu, d, off);
        }
        if (lane == 0) {
            float ss = s + g_cs[0], dd = d + g_cs[1];
#pragma unroll
            for (int k = 0; k < 12; k++) {
                ss = fmaf(cn[i][k], g_vs[k], ss);
                dd = fmaf(cn[i][k], g_vd[k], dd);
            }
            g_als[r0 + i] = ss;
            g_ald[r0 + i] = dd;
        }
    }
}

// ---------------- K2: GAT aggregation + fused GRU — 2 nodes x 4 batches per block ----------------
__global__ void __launch_bounds__(256) k_agg(const float* __restrict__ hcur,
                                             const float* __restrict__ bg,
                                             float* __restrict__ out) {
    __shared__ int   sedge[2][PAD];
    __shared__ float sp[2][4][PAD];
    int tid = threadIdx.x;

    // zero g_mom for next replay (k_agg never reads it)
    {
        int z = blockIdx.x * 256 + tid;
        if (z < 12 * 1296) g_mom[z] = 0.f;
    }

    int warp = tid >> 5, lane = tid & 31;
    int sub = warp >> 2;
    int bq  = warp & 3;
    int node = blockIdx.x * 2 + sub;

    int deg = g_deg[node];
    const int* row = g_epad + node * PAD;
    if (bq == 0) {
        for (int i = lane; i < deg; i += 32) sedge[sub][i] = row[i];
    }
    __syncthreads();

    const float* als = g_als + bq * NN;
    float aldn = g_ald[bq * NN + node];

    float den = 0.f;
    for (int i = lane; i < deg; i += 32) {
        int s = sedge[sub][i];
        float ev = als[s] + aldn;
        ev = (ev >= 0.f) ? ev : 0.2f * ev;
        float p = ex2a(ev);
        sp[sub][bq][i] = p;
        den += p;
    }
#pragma unroll
    for (int off = 16; off; off >>= 1) den += __shfl_xor_sync(0xffffffffu, den, off);
    __syncwarp();

    float4 acc = make_float4(0.f, 0.f, 0.f, 0.f);
    const __half* xb = g_xzn + (size_t)bq * NN * 128;
#pragma unroll 4
    for (int e = 0; e < deg; e++) {
        int s = sedge[sub][e];
        float p = sp[sub][bq][e];
        uint2 v = *reinterpret_cast<const uint2*>(xb + (size_t)s * 128 + lane * 4);
        float2 f0 = __half22float2(*reinterpret_cast<const __half2*>(&v.x));
        float2 f1 = __half22float2(*reinterpret_cast<const __half2*>(&v.y));
        acc.x = fmaf(p, f0.x, acc.x);
        acc.y = fmaf(p, f0.y, acc.y);
        acc.z = fmaf(p, f1.x, acc.z);
        acc.w = fmaf(p, f1.y, acc.w);
    }
    float inv = 1.0f / (den + 1e-16f);
    int col = lane * 4;
    float v0 = acc.x * inv + bg[64 + col + 0];
    float v1 = acc.y * inv + bg[64 + col + 1];
    float v2 = acc.z * inv + bg[64 + col + 2];
    float v3 = acc.w * inv + bg[64 + col + 3];

    float a0, a1, a2, a3;
    if (lane < 16) {
        a0 = 1.0f / (1.0f + __expf(-v0));
        a1 = 1.0f / (1.0f + __expf(-v1));
        a2 = 1.0f / (1.0f + __expf(-v2));
        a3 = 1.0f / (1.0f + __expf(-v3));
    } else {
        a0 = tanhf(v0); a1 = tanhf(v1); a2 = tanhf(v2); a3 = tanhf(v3);
    }
    float n0 = __shfl_down_sync(0xffffffffu, a0, 16);
    float n1 = __shfl_down_sync(0xffffffffu, a1, 16);
    float n2 = __shfl_down_sync(0xffffffffu, a2, 16);
    float n3 = __shfl_down_sync(0xffffffffu, a3, 16);
    if (lane < 16) {
        const float4 h4 =
            *reinterpret_cast<const float4*>(hcur + ((size_t)bq * NN + node) * HH + lane * 4);
        float4 o;
        o.x = (1.f - a0) * n0 + a0 * h4.x;
        o.y = (1.f - a1) * n1 + a1 * h4.y;
        o.z = (1.f - a2) * n2 + a2 * h4.z;
        o.w = (1.f - a3) * n3 + a3 * h4.w;
        *reinterpret_cast<float4*>(out + ((size_t)bq * NN + node) * HH + lane * 4) = o;
    }
}

// ---------------- launch ----------------
extern "C" void kernel_launch(void* const* d_in, const int* in_sizes, int n_in,
                              void* d_out, int out_size) {
    const float* in   = (const float*)d_in[0];
    const float* hcur = (const float*)d_in[1];
    const int*   edge = (const int*)d_in[2];
    const float* Wq_a = (const float*)d_in[3];
    const float* bq_a = (const float*)d_in[4];
    const float* Wk_a = (const float*)d_in[5];
    const float* bk_a = (const float*)d_in[6];
    const float* Wv_a = (const float*)d_in[7];
    const float* bv_a = (const float*)d_in[8];
    const float* Wq_b = (const float*)d_in[9];
    const float* bq_b = (const float*)d_in[10];
    const float* Wk_b = (const float*)d_in[11];
    const float* bk_b = (const float*)d_in[12];
    const float* Wv_b = (const float*)d_in[13];
    const float* bv_b = (const float*)d_in[14];
    const float* Wq_c = (const float*)d_in[15];
    const float* bq_c = (const float*)d_in[16];
    const float* Wk_c = (const float*)d_in[17];
    const float* bk_c = (const float*)d_in[18];
    const float* Wv_c = (const float*)d_in[19];
    const float* bv_c = (const float*)d_in[20];
    const float* Wg      = (const float*)d_in[21];
    const float* att_src = (const float*)d_in[22];
    const float* att_dst = (const float*)d_in[23];
    const float* bg      = (const float*)d_in[24];
    float* out = (float*)d_out;

    k_pre<<<163, 256>>>(in, edge,
                        Wq_a, bq_a, Wk_a, bk_a, Wq_b, bq_b, Wk_b, bk_b,
                        Wq_c, bq_c, Wk_c, bk_c,
                        Wv_a, bv_a, Wv_b, bv_b, Wv_c, bv_c,
                        Wg, att_src, att_dst);
    k_xzn<<<500, 256>>>(in, hcur, Wg);
    k_agg<<<1000, 256>>>(hcur, bg, out);
}